// round 14
// baseline (speedup 1.0000x reference)
#include <cuda_runtime.h>
#include <math.h>

#define NUM_CLASSES 1000
#define FEAT_DIM    256
#define NROWS       262144
#define ALPHA       0.5f

#define SORT_BLK  148     // one block per SM; all co-resident in wave 1
#define SORT_TPB  1024
#define SORT_RPB  1772    // ceil(NROWS / SORT_BLK); last block gets fewer

// ---- scratch (device globals; zero-init; finalize restores zeros) ---------
__device__ float g_sums[NUM_CLASSES * FEAT_DIM];
__device__ float g_counts[NUM_CLASSES];
__device__ int   g_tot[NUM_CLASSES];     // class totals (reset by finalize)
__device__ int   g_sorted[NROWS];        // (label<<18) | row
__device__ float g_loss;                 // reset by finalize
__device__ int   g_sync[2];              // grid barrier counters (reset by finalize)

__device__ __forceinline__ void grid_sync(int slot) {
    __syncthreads();
    if (threadIdx.x == 0) {
        __threadfence();
        atomicAdd(&g_sync[slot], 1);
        while (atomicAdd(&g_sync[slot], 0) < SORT_BLK) __nanosleep(32);
        __threadfence();
    }
    __syncthreads();
}

// ---------------------------------------------------------------------------
// K1: counting-group kernel (148 blocks, 1/SM).
//  A: block smem hist; res[c] = atomicAdd(&g_tot[c], cnt) (return = block's
//     within-class offset).  B: hierarchical warp scan of totals -> bases;
//     scatter through smem cursors.
// ---------------------------------------------------------------------------
__global__ void __launch_bounds__(SORT_TPB)
cl_sort_kernel(const void* __restrict__ labels_raw) {
    __shared__ int sh_hist[1024];
    __shared__ int sh_res[1024];
    __shared__ int sh_cur[1024];
    __shared__ int sh_wsum[32];
    __shared__ int sh_is64;
    const int t = threadIdx.x;
    const int bid = blockIdx.x;
    const int lane = t & 31;
    const int wid = t >> 5;

    // ---- phase A: zero hist + branch-free dtype detect (warp 0 only) ----
    sh_hist[t] = 0;
    if (wid == 0) {
        // int64 labels < 1000 -> all odd 32-bit words zero. OR 64 odd words
        // with full MLP (no break), reduce with __any_sync.
        const int* w = (const int*)labels_raw;
        int v = w[2 * lane + 1] | w[2 * (lane + 32) + 1];
        int any = __any_sync(0xFFFFFFFFu, v != 0);
        if (lane == 0) sh_is64 = !any;
    }
    __syncthreads();
    const int is64 = sh_is64;

    const long long* lab64 = (const long long*)labels_raw;
    const int*       lab32 = (const int*)labels_raw;

    const int base = bid * SORT_RPB;
    const int nrow = (base + SORT_RPB <= NROWS) ? SORT_RPB : (NROWS - base);

    // two row slots per thread (SORT_RPB <= 2*SORT_TPB)
    int l0 = -1, l1 = -1;
    if (t < nrow)              l0 = is64 ? (int)lab64[base + t]
                                         : lab32[base + t];
    if (t + SORT_TPB < nrow)   l1 = is64 ? (int)lab64[base + SORT_TPB + t]
                                         : lab32[base + SORT_TPB + t];
    if (l0 >= 0) atomicAdd(&sh_hist[l0], 1);
    if (l1 >= 0) atomicAdd(&sh_hist[l1], 1);
    __syncthreads();
    {
        int cnt = (t < NUM_CLASSES) ? sh_hist[t] : 0;
        int res = 0;
        if (cnt > 0) res = atomicAdd(&g_tot[t], cnt);  // return = my offset
        sh_res[t] = res;
    }

    grid_sync(0);

    // ---- phase B: hierarchical scan of totals (2 barriers) + scatter ----
    int v = (t < NUM_CLASSES) ? __ldcg(&g_tot[t]) : 0;
    int incl = v;
    #pragma unroll
    for (int o = 1; o < 32; o <<= 1) {
        int n = __shfl_up_sync(0xFFFFFFFFu, incl, o);
        if (lane >= o) incl += n;
    }
    if (lane == 31) sh_wsum[wid] = incl;
    __syncthreads();
    if (wid == 0) {
        int ws = sh_wsum[lane];
        int wincl = ws;
        #pragma unroll
        for (int o = 1; o < 32; o <<= 1) {
            int n = __shfl_up_sync(0xFFFFFFFFu, wincl, o);
            if (lane >= o) wincl += n;
        }
        sh_wsum[lane] = wincl - ws;   // exclusive warp prefix
    }
    __syncthreads();
    if (t < NUM_CLASSES) {
        int excl = sh_wsum[wid] + incl - v;        // global exclusive base
        if (bid == 0) g_counts[t] = (float)v;
        sh_cur[t] = excl + sh_res[t];              // block-local cursor
    }
    __syncthreads();
    if (l0 >= 0) {
        int pos = atomicAdd(&sh_cur[l0], 1);
        g_sorted[pos] = (l0 << 18) | (base + t);
    }
    if (l1 >= 0) {
        int pos = atomicAdd(&sh_cur[l1], 1);
        g_sorted[pos] = (l1 << 18) | (base + SORT_TPB + t);
    }
}

// Vectorized reduction-add to global (sm_90+)
__device__ __forceinline__ void red_add_v4(float* addr, float4 v) {
    asm volatile("red.global.add.v4.f32 [%0], {%1, %2, %3, %4};"
                 :: "l"(addr), "f"(v.x), "f"(v.y), "f"(v.z), "f"(v.w)
                 : "memory");
}
__device__ __forceinline__ float4 f4add(float4 a, float4 b) {
    return make_float4(a.x + b.x, a.y + b.y, a.z + b.z, a.w + b.w);
}

// ---------------------------------------------------------------------------
// K2: main fused pass. 4-row groups for MLP; register-aggregated segment sums.
// ---------------------------------------------------------------------------
#define MAIN_BLOCKS 1184
#define MAIN_THREADS 256
#define TOTAL_WARPS (MAIN_BLOCKS * (MAIN_THREADS / 32))
#define CHUNK ((NROWS + TOTAL_WARPS - 1) / TOTAL_WARPS)   // 28 (<= 32 required)

__global__ void __launch_bounds__(MAIN_THREADS)
cl_main_kernel(const float* __restrict__ x,
               const float* __restrict__ centers) {
    __shared__ float s_loss;
    if (threadIdx.x == 0) s_loss = 0.0f;
    __syncthreads();

    const int lane  = threadIdx.x & 31;
    const int gwarp = blockIdx.x * (MAIN_THREADS / 32) + (threadIdx.x >> 5);
    const int pos0  = gwarp * CHUNK;
    int cnt = NROWS - pos0;
    if (cnt > CHUNK) cnt = CHUNK;

    int ent = 0;
    if (pos0 < NROWS && lane < cnt) ent = g_sorted[pos0 + lane];

    float loss_acc = 0.0f;
    float4 acc_a = make_float4(0.f, 0.f, 0.f, 0.f);
    float4 acc_b = make_float4(0.f, 0.f, 0.f, 0.f);
    float4 ca = acc_a, cb = acc_b;
    int cur_lbl = -1;

    int i = 0;
    for (; i + 4 <= cnt; i += 4) {
        int lbl[4], row[4];
        #pragma unroll
        for (int r = 0; r < 4; r++) {
            int e = __shfl_sync(0xFFFFFFFFu, ent, i + r);
            lbl[r] = e >> 18;
            row[r] = e & 0x3FFFF;
        }
        float4 xa[4], xb[4];
        #pragma unroll
        for (int r = 0; r < 4; r++) {
            const float4* __restrict__ xr =
                (const float4*)(x + (size_t)row[r] * FEAT_DIM);
            xa[r] = __ldcs(xr + lane);
            xb[r] = __ldcs(xr + lane + 32);
        }

        float ss[4];
        #pragma unroll
        for (int r = 0; r < 4; r++) {
            if (lbl[r] != cur_lbl) {
                if (cur_lbl >= 0) {
                    float* b = g_sums + (size_t)cur_lbl * FEAT_DIM;
                    red_add_v4(b + lane * 4, acc_a);
                    red_add_v4(b + 128 + lane * 4, acc_b);
                    acc_a = make_float4(0.f, 0.f, 0.f, 0.f);
                    acc_b = make_float4(0.f, 0.f, 0.f, 0.f);
                }
                const float4* cr = (const float4*)(centers + (size_t)lbl[r] * FEAT_DIM);
                ca = cr[lane]; cb = cr[lane + 32];
                cur_lbl = lbl[r];
            }
            acc_a = f4add(acc_a, xa[r]);
            acc_b = f4add(acc_b, xb[r]);
            float d0 = xa[r].x-ca.x, d1 = xa[r].y-ca.y,
                  d2 = xa[r].z-ca.z, d3 = xa[r].w-ca.w;
            float f0 = xb[r].x-cb.x, f1 = xb[r].y-cb.y,
                  f2 = xb[r].z-cb.z, f3 = xb[r].w-cb.w;
            ss[r] = d0*d0+d1*d1+d2*d2+d3*d3 + f0*f0+f1*f1+f2*f2+f3*f3;
        }

        #pragma unroll
        for (int o = 16; o > 0; o >>= 1) {
            #pragma unroll
            for (int r = 0; r < 4; r++)
                ss[r] += __shfl_xor_sync(0xFFFFFFFFu, ss[r], o);
        }
        if (lane == 0)
            loss_acc += (sqrtf(ss[0]) + sqrtf(ss[1]))
                      + (sqrtf(ss[2]) + sqrtf(ss[3]));
    }

    for (; i < cnt; i++) {
        int e = __shfl_sync(0xFFFFFFFFu, ent, i);
        int lbl = e >> 18, row = e & 0x3FFFF;
        const float4* __restrict__ xr = (const float4*)(x + (size_t)row * FEAT_DIM);
        float4 xa = __ldcs(xr + lane), xb = __ldcs(xr + lane + 32);
        if (lbl != cur_lbl) {
            if (cur_lbl >= 0) {
                float* b = g_sums + (size_t)cur_lbl * FEAT_DIM;
                red_add_v4(b + lane * 4, acc_a);
                red_add_v4(b + 128 + lane * 4, acc_b);
                acc_a = make_float4(0.f, 0.f, 0.f, 0.f);
                acc_b = make_float4(0.f, 0.f, 0.f, 0.f);
            }
            const float4* cr = (const float4*)(centers + (size_t)lbl * FEAT_DIM);
            ca = cr[lane]; cb = cr[lane + 32];
            cur_lbl = lbl;
        }
        acc_a = f4add(acc_a, xa);
        acc_b = f4add(acc_b, xb);
        float d0 = xa.x-ca.x, d1 = xa.y-ca.y, d2 = xa.z-ca.z, d3 = xa.w-ca.w;
        float f0 = xb.x-cb.x, f1 = xb.y-cb.y, f2 = xb.z-cb.z, f3 = xb.w-cb.w;
        float ss = d0*d0+d1*d1+d2*d2+d3*d3 + f0*f0+f1*f1+f2*f2+f3*f3;
        #pragma unroll
        for (int o = 16; o > 0; o >>= 1)
            ss += __shfl_xor_sync(0xFFFFFFFFu, ss, o);
        if (lane == 0) loss_acc += sqrtf(ss);
    }

    if (cur_lbl >= 0) {
        float* b = g_sums + (size_t)cur_lbl * FEAT_DIM;
        red_add_v4(b + lane * 4, acc_a);
        red_add_v4(b + 128 + lane * 4, acc_b);
    }

    if (lane == 0) atomicAdd(&s_loss, loss_acc);
    __syncthreads();
    if (threadIdx.x == 0) atomicAdd(&g_loss, s_loss);
}

// ---------------------------------------------------------------------------
// K3: finalize + restore ALL scratch to zero for the next graph replay.
// ---------------------------------------------------------------------------
__global__ void cl_finalize_kernel(const float* __restrict__ centers,
                                   float* __restrict__ out) {
    int i = blockIdx.x * blockDim.x + threadIdx.x;
    if (i == 0) { out[0] = g_loss * (0.5f / (float)NROWS); g_loss = 0.0f; }
    if (i < 2) g_sync[i] = 0;
    if (i < NUM_CLASSES) g_tot[i] = 0;
    if (i < NUM_CLASSES * FEAT_DIM) {
        int c = i / FEAT_DIM;
        float cnt = g_counts[c];
        float cen = centers[i];
        float res = cen;
        if (cnt > 0.0f) {
            float mean = g_sums[i] / cnt;
            res = cen + ALPHA * (mean - cen);
        }
        out[1 + i] = res;
        g_sums[i] = 0.0f;                 // re-zero for next replay
    }
}

// ---------------------------------------------------------------------------
extern "C" void kernel_launch(void* const* d_in, const int* in_sizes, int n_in,
                              void* d_out, int out_size) {
    const float* x       = (const float*)d_in[0];
    const void*  labels  = d_in[1];
    const float* centers = (const float*)d_in[2];
    float*       out     = (float*)d_out;
    (void)in_sizes; (void)n_in; (void)out_size;

    cl_sort_kernel    <<<SORT_BLK, SORT_TPB>>>(labels);
    cl_main_kernel    <<<MAIN_BLOCKS, MAIN_THREADS>>>(x, centers);
    cl_finalize_kernel<<<(NUM_CLASSES * FEAT_DIM + 256) / 256, 256>>>(centers, out);
}

// round 16
// speedup vs baseline: 1.0298x; 1.0298x over previous
#include <cuda_runtime.h>
#include <math.h>

#define NUM_CLASSES 1000
#define FEAT_DIM    256
#define NROWS       262144
#define ALPHA       0.5f

#define SORT_BLK  148     // one block per SM; all co-resident in wave 1
#define SORT_TPB  1024
#define SORT_RPB  1772    // ceil(NROWS / SORT_BLK); last block gets fewer

// ---- scratch (device globals; zero-init; self-maintaining across replays) -
__device__ float g_sums[NUM_CLASSES * FEAT_DIM];   // re-zeroed by main epilogue
__device__ float g_counts[NUM_CLASSES];
__device__ int   g_tot[NUM_CLASSES];               // re-zeroed by main epilogue
__device__ int   g_sorted[NROWS];
__device__ float g_loss;                           // re-zeroed by main epilogue
__device__ int   g_cnt[2];                         // sense-reversing barrier state
__device__ int   g_sense[2];                       // (never needs external reset)

// Sense-reversing grid barrier: replay-safe, no reset required.
__device__ __forceinline__ void grid_sync(int slot, int nblk) {
    __syncthreads();
    if (threadIdx.x == 0) {
        int s = atomicAdd(&g_sense[slot], 0);     // my sense before arriving
        __threadfence();                           // release my writes
        int old = atomicAdd(&g_cnt[slot], 1);
        if (old == nblk - 1) {
            g_cnt[slot] = 0;                       // safe: all have arrived
            __threadfence();
            atomicExch(&g_sense[slot], s ^ 1);     // release everyone
        } else {
            while (atomicAdd(&g_sense[slot], 0) == s) __nanosleep(32);
        }
        __threadfence();                           // acquire
    }
    __syncthreads();
}

// ---------------------------------------------------------------------------
// K1: counting-group kernel (148 blocks, 1/SM). Phase A: hist + fused
// total/reservation atomic. Phase B: hierarchical scan of totals + scatter.
// ---------------------------------------------------------------------------
__global__ void __launch_bounds__(SORT_TPB)
cl_sort_kernel(const void* __restrict__ labels_raw) {
    __shared__ int sh_hist[1024];
    __shared__ int sh_res[1024];
    __shared__ int sh_cur[1024];
    __shared__ int sh_wsum[32];
    __shared__ int sh_is64;
    const int t = threadIdx.x;
    const int bid = blockIdx.x;
    const int lane = t & 31;
    const int wid = t >> 5;

    // zero hist + branch-free dtype detect (warp 0 only)
    sh_hist[t] = 0;
    if (wid == 0) {
        const int* w = (const int*)labels_raw;
        int v = w[2 * lane + 1] | w[2 * (lane + 32) + 1];
        int any = __any_sync(0xFFFFFFFFu, v != 0);
        if (lane == 0) sh_is64 = !any;
    }
    __syncthreads();
    const int is64 = sh_is64;

    const long long* lab64 = (const long long*)labels_raw;
    const int*       lab32 = (const int*)labels_raw;

    const int base = bid * SORT_RPB;
    const int nrow = (base + SORT_RPB <= NROWS) ? SORT_RPB : (NROWS - base);

    int l0 = -1, l1 = -1;
    if (t < nrow)            l0 = is64 ? (int)lab64[base + t] : lab32[base + t];
    if (t + SORT_TPB < nrow) l1 = is64 ? (int)lab64[base + SORT_TPB + t]
                                       : lab32[base + SORT_TPB + t];
    if (l0 >= 0) atomicAdd(&sh_hist[l0], 1);
    if (l1 >= 0) atomicAdd(&sh_hist[l1], 1);
    __syncthreads();
    {
        int cnt = (t < NUM_CLASSES) ? sh_hist[t] : 0;
        int res = 0;
        if (cnt > 0) res = atomicAdd(&g_tot[t], cnt);  // return = my offset
        sh_res[t] = res;
    }

    grid_sync(0, SORT_BLK);

    // hierarchical scan of totals (2 barriers) + scatter
    int v = (t < NUM_CLASSES) ? __ldcg(&g_tot[t]) : 0;
    int incl = v;
    #pragma unroll
    for (int o = 1; o < 32; o <<= 1) {
        int n = __shfl_up_sync(0xFFFFFFFFu, incl, o);
        if (lane >= o) incl += n;
    }
    if (lane == 31) sh_wsum[wid] = incl;
    __syncthreads();
    if (wid == 0) {
        int ws = sh_wsum[lane];
        int wincl = ws;
        #pragma unroll
        for (int o = 1; o < 32; o <<= 1) {
            int n = __shfl_up_sync(0xFFFFFFFFu, wincl, o);
            if (lane >= o) wincl += n;
        }
        sh_wsum[lane] = wincl - ws;
    }
    __syncthreads();
    if (t < NUM_CLASSES) {
        int excl = sh_wsum[wid] + incl - v;
        if (bid == 0) g_counts[t] = (float)v;
        sh_cur[t] = excl + sh_res[t];
    }
    __syncthreads();
    if (l0 >= 0) {
        int pos = atomicAdd(&sh_cur[l0], 1);
        g_sorted[pos] = (l0 << 18) | (base + t);
    }
    if (l1 >= 0) {
        int pos = atomicAdd(&sh_cur[l1], 1);
        g_sorted[pos] = (l1 << 18) | (base + SORT_TPB + t);
    }
}

// Vectorized reduction-add to global (sm_90+)
__device__ __forceinline__ void red_add_v4(float* addr, float4 v) {
    asm volatile("red.global.add.v4.f32 [%0], {%1, %2, %3, %4};"
                 :: "l"(addr), "f"(v.x), "f"(v.y), "f"(v.z), "f"(v.w)
                 : "memory");
}
__device__ __forceinline__ float4 f4add(float4 a, float4 b) {
    return make_float4(a.x + b.x, a.y + b.y, a.z + b.z, a.w + b.w);
}

// ---------------------------------------------------------------------------
// K2: main fused pass + FUSED FINALIZE (grid barrier, then epilogue).
// 592 blocks = 148 SMs x 4 resident (reg cap 64 via launch bounds).
// Chunk = 56 rows/warp, preloaded into two registers per lane.
// ---------------------------------------------------------------------------
#define MAIN_BLOCKS 592
#define MAIN_THREADS 256
#define TOTAL_WARPS (MAIN_BLOCKS * (MAIN_THREADS / 32))          // 4736
#define CHUNK ((NROWS + TOTAL_WARPS - 1) / TOTAL_WARPS)          // 56 (<= 64)

__global__ void __launch_bounds__(MAIN_THREADS, 4)
cl_main_kernel(const float* __restrict__ x,
               const float* __restrict__ centers,
               float* __restrict__ out) {
    __shared__ float s_loss;
    if (threadIdx.x == 0) s_loss = 0.0f;
    __syncthreads();

    const int lane  = threadIdx.x & 31;
    const int gwarp = blockIdx.x * (MAIN_THREADS / 32) + (threadIdx.x >> 5);
    const int pos0  = gwarp * CHUNK;
    int cnt = NROWS - pos0;
    if (cnt > CHUNK) cnt = CHUNK;
    if (cnt < 0) cnt = 0;

    // preload chunk: 2 coalesced LDGs (entries 0..31 and 32..55)
    int ent0 = 0, ent1 = 0;
    if (pos0 < NROWS) {
        if (lane < cnt)      ent0 = g_sorted[pos0 + lane];
        if (32 + lane < cnt) ent1 = g_sorted[pos0 + 32 + lane];
    }

    float loss_acc = 0.0f;
    float4 acc_a = make_float4(0.f, 0.f, 0.f, 0.f);
    float4 acc_b = make_float4(0.f, 0.f, 0.f, 0.f);
    float4 ca = acc_a, cb = acc_b;
    int cur_lbl = -1;

    int i = 0;
    for (; i + 4 <= cnt; i += 4) {
        int lbl[4], row[4];
        #pragma unroll
        for (int r = 0; r < 4; r++) {
            int idx = i + r;   // uniform across warp
            int e = (idx < 32) ? __shfl_sync(0xFFFFFFFFu, ent0, idx)
                               : __shfl_sync(0xFFFFFFFFu, ent1, idx - 32);
            lbl[r] = e >> 18;
            row[r] = e & 0x3FFFF;
        }
        float4 xa[4], xb[4];
        #pragma unroll
        for (int r = 0; r < 4; r++) {
            const float4* __restrict__ xr =
                (const float4*)(x + (size_t)row[r] * FEAT_DIM);
            xa[r] = __ldcs(xr + lane);
            xb[r] = __ldcs(xr + lane + 32);
        }

        float ss[4];
        #pragma unroll
        for (int r = 0; r < 4; r++) {
            if (lbl[r] != cur_lbl) {
                if (cur_lbl >= 0) {
                    float* b = g_sums + (size_t)cur_lbl * FEAT_DIM;
                    red_add_v4(b + lane * 4, acc_a);
                    red_add_v4(b + 128 + lane * 4, acc_b);
                    acc_a = make_float4(0.f, 0.f, 0.f, 0.f);
                    acc_b = make_float4(0.f, 0.f, 0.f, 0.f);
                }
                const float4* cr = (const float4*)(centers + (size_t)lbl[r] * FEAT_DIM);
                ca = cr[lane]; cb = cr[lane + 32];
                cur_lbl = lbl[r];
            }
            acc_a = f4add(acc_a, xa[r]);
            acc_b = f4add(acc_b, xb[r]);
            float d0 = xa[r].x-ca.x, d1 = xa[r].y-ca.y,
                  d2 = xa[r].z-ca.z, d3 = xa[r].w-ca.w;
            float f0 = xb[r].x-cb.x, f1 = xb[r].y-cb.y,
                  f2 = xb[r].z-cb.z, f3 = xb[r].w-cb.w;
            ss[r] = d0*d0+d1*d1+d2*d2+d3*d3 + f0*f0+f1*f1+f2*f2+f3*f3;
        }

        #pragma unroll
        for (int o = 16; o > 0; o >>= 1) {
            #pragma unroll
            for (int r = 0; r < 4; r++)
                ss[r] += __shfl_xor_sync(0xFFFFFFFFu, ss[r], o);
        }
        if (lane == 0)
            loss_acc += (sqrtf(ss[0]) + sqrtf(ss[1]))
                      + (sqrtf(ss[2]) + sqrtf(ss[3]));
    }

    for (; i < cnt; i++) {
        int e = (i < 32) ? __shfl_sync(0xFFFFFFFFu, ent0, i)
                         : __shfl_sync(0xFFFFFFFFu, ent1, i - 32);
        int lbl = e >> 18, row = e & 0x3FFFF;
        const float4* __restrict__ xr = (const float4*)(x + (size_t)row * FEAT_DIM);
        float4 xa = __ldcs(xr + lane), xb = __ldcs(xr + lane + 32);
        if (lbl != cur_lbl) {
            if (cur_lbl >= 0) {
                float* b = g_sums + (size_t)cur_lbl * FEAT_DIM;
                red_add_v4(b + lane * 4, acc_a);
                red_add_v4(b + 128 + lane * 4, acc_b);
                acc_a = make_float4(0.f, 0.f, 0.f, 0.f);
                acc_b = make_float4(0.f, 0.f, 0.f, 0.f);
            }
            const float4* cr = (const float4*)(centers + (size_t)lbl * FEAT_DIM);
            ca = cr[lane]; cb = cr[lane + 32];
            cur_lbl = lbl;
        }
        acc_a = f4add(acc_a, xa);
        acc_b = f4add(acc_b, xb);
        float d0 = xa.x-ca.x, d1 = xa.y-ca.y, d2 = xa.z-ca.z, d3 = xa.w-ca.w;
        float f0 = xb.x-cb.x, f1 = xb.y-cb.y, f2 = xb.z-cb.z, f3 = xb.w-cb.w;
        float ss = d0*d0+d1*d1+d2*d2+d3*d3 + f0*f0+f1*f1+f2*f2+f3*f3;
        #pragma unroll
        for (int o = 16; o > 0; o >>= 1)
            ss += __shfl_xor_sync(0xFFFFFFFFu, ss, o);
        if (lane == 0) loss_acc += sqrtf(ss);
    }

    if (cur_lbl >= 0) {
        float* b = g_sums + (size_t)cur_lbl * FEAT_DIM;
        red_add_v4(b + lane * 4, acc_a);
        red_add_v4(b + 128 + lane * 4, acc_b);
    }

    if (lane == 0) atomicAdd(&s_loss, loss_acc);
    __syncthreads();
    if (threadIdx.x == 0) atomicAdd(&g_loss, s_loss);

    // ---- fused finalize: wait for all blocks, then epilogue + resets ----
    grid_sync(1, MAIN_BLOCKS);

    const int gid = blockIdx.x * MAIN_THREADS + threadIdx.x;
    if (gid == 0) { out[0] = g_loss * (0.5f / (float)NROWS); g_loss = 0.0f; }
    if (gid < NUM_CLASSES) g_tot[gid] = 0;
    for (int j = gid; j < NUM_CLASSES * FEAT_DIM; j += MAIN_BLOCKS * MAIN_THREADS) {
        int c = j / FEAT_DIM;
        float cn = g_counts[c];
        float cen = centers[j];
        float res = cen;
        if (cn > 0.0f) {
            float mean = g_sums[j] / cn;
            res = cen + ALPHA * (mean - cen);
        }
        out[1 + j] = res;
        g_sums[j] = 0.0f;                 // re-zero for next replay
    }
}

// ---------------------------------------------------------------------------
extern "C" void kernel_launch(void* const* d_in, const int* in_sizes, int n_in,
                              void* d_out, int out_size) {
    const float* x       = (const float*)d_in[0];
    const void*  labels  = d_in[1];
    const float* centers = (const float*)d_in[2];
    float*       out     = (float*)d_out;
    (void)in_sizes; (void)n_in; (void)out_size;

    cl_sort_kernel<<<SORT_BLK, SORT_TPB>>>(labels);
    cl_main_kernel<<<MAIN_BLOCKS, MAIN_THREADS>>>(x, centers, out);
}